// round 6
// baseline (speedup 1.0000x reference)
#include <cuda_runtime.h>

// B=4, H=256, W=256 torus. mu-subsystem only. Persistent kernel:
// constants register-resident for all 100 iterations; 13 halo-recompute
// periods (12 x T=8 + 1 x T=4) separated by a software global barrier.
#define BHW 262144
#define NBLOCKS 256

__device__ float  g_mu[2][BHW];   // mu ping-pong (per period)
__device__ float  g_v [2][BHW];   // momentum ping-pong
__device__ float4 g_c [BHW];      // (ex, ey, eu0, el1)
__device__ float2 g_ac[BHW];      // (2*uw1, uw2*y)
__device__ unsigned g_bar;        // global barrier counter

// ---------------- init: pack per-pixel constants ----------------
__global__ __launch_bounds__(256) void init_kernel(const float* __restrict__ y,
                                                   const float2* __restrict__ ew2,
                                                   const float2* __restrict__ un2) {
    const int p = blockIdx.x * 256 + threadIdx.x;
    const int base = p & ~65535;
    const int i    = p &  65535;
    const int row  = i & ~255;
    const int pu = base | ((i + 65280) & 65535);
    const int pl = base | row | ((i + 255) & 255);

    const float yv = y[p];
    const float2 e  = ew2[p];
    const float  eu = ew2[pu].x;
    const float  el = ew2[pl].y;
    const float2 u  = un2[p];

    g_mu[0][p] = yv;
    g_v [0][p] = 0.0f;
    g_c [p]    = make_float4(e.x, e.y, eu, el);
    g_ac[p]    = make_float2(2.0f * u.x, u.y * yv);
    if (p == 0) g_bar = 0u;
}

// ---------------- persistent kernel ----------------
// Block = 8 warps stacked vertically; warp holds 10 rows x 32 cols in regs.
// Region 80x32, interior (exact after T<=8 iters): rows 8..71, cols 8..23.
__global__ __launch_bounds__(256, 2) void persist_kernel(float* __restrict__ out) {
    __shared__ float s_top[2][8][32];
    __shared__ float s_bot[2][8][32];

    const int lane = threadIdx.x & 31;
    const int w    = threadIdx.x >> 5;
    const int blk  = blockIdx.x;                 // 4 img x 4 vtile x 16 htile
    const int base = (blk >> 6) << 16;
    const int tv   = (blk >> 4) & 3;
    const int th   = blk & 15;
    const int gcol = (th * 16 - 8 + lane) & 255;
    const int r0   = tv * 64 - 8 + w * 10;

    // cz[r] == cx[r-1] (up-neighbor's down-edge weight is my own constant
    // one row above); only row 0 needs an explicit cz0 load.
    float mu[10], v[10], cx[10], cy[10], cw[10], ax[10], ay[10], cz0;

    #pragma unroll
    for (int r = 0; r < 10; ++r) {
        const int p = base + (((r0 + r) & 255) << 8) + gcol;
        mu[r] = g_mu[0][p];
        v[r]  = g_v[0][p];
        const float4 c = g_c[p];
        cx[r] = c.x; cy[r] = c.y; cw[r] = c.w;
        if (r == 0) cz0 = c.z;
        const float2 a = g_ac[p];
        ax[r] = a.x; ay[r] = a.y;
    }

    unsigned target = 0;
    for (int per = 0; per < 13; ++per) {
        const int TT = (per < 12) ? 8 : 4;

        s_top[0][w][lane] = mu[0];
        s_bot[0][w][lane] = mu[9];
        __syncthreads();

        for (int it = 0; it < TT; ++it) {
            const int rb = it & 1;
            float old_above = (w > 0) ? s_bot[rb][w - 1][lane] : mu[0];
            const float dn  = (w < 7) ? s_top[rb][w + 1][lane] : mu[9];

            #pragma unroll
            for (int r = 0; r < 10; ++r) {
                const float cur   = mu[r];
                const float below = (r < 9) ? mu[r + 1] : dn;
                const float left  = __shfl_up_sync(0xFFFFFFFFu, cur, 1);
                const float right = __shfl_down_sync(0xFFFFFFFFu, cur, 1);
                const float czr   = (r == 0) ? cz0 : cx[r - 1];

                float dmu = fmaf(ax[r], cur, ay[r]);
                dmu = fmaf(cx[r], below, dmu);
                dmu = fmaf(cy[r], right, dmu);
                dmu = fmaf(czr,  old_above, dmu);
                dmu = fmaf(cw[r], left, dmu);

                v[r]  = fmaf(0.7f, v[r], 0.01f * dmu);
                mu[r] = fminf(fmaxf(cur + v[r], 0.0f), 63.0f);
                old_above = cur;
            }
            s_top[rb ^ 1][w][lane] = mu[0];
            s_bot[rb ^ 1][w][lane] = mu[9];
            __syncthreads();
        }

        const int d = (per + 1) & 1;

        // Write exact interior (distance >= 8 from region edge; T<=8).
        if (lane >= 8 && lane < 24) {
            #pragma unroll
            for (int r = 0; r < 10; ++r) {
                const int R = w * 10 + r;
                if (R >= 8 && R < 72) {
                    const int p = base + (((r0 + r) & 255) << 8) + gcol;
                    g_mu[d][p] = mu[r];
                    g_v [d][p] = v[r];
                    if (per == 12) out[p] = mu[r];
                }
            }
        }

        if (per == 12) break;

        // ---- global barrier: release writes, arrive, acquire-spin ----
        __threadfence();
        __syncthreads();
        target += NBLOCKS;
        if (threadIdx.x == 0) {
            atomicAdd(&g_bar, 1u);
            while (*((volatile unsigned*)&g_bar) < target) { }
            __threadfence();
        }
        __syncthreads();

        // Reload halo cells' mu,v (interior stays in registers).
        #pragma unroll
        for (int r = 0; r < 10; ++r) {
            const int R = w * 10 + r;
            const bool interior = (R >= 8) && (R < 72) && (lane >= 8) && (lane < 24);
            if (!interior) {
                const int p = base + (((r0 + r) & 255) << 8) + gcol;
                mu[r] = g_mu[d][p];
                v[r]  = g_v[d][p];
            }
        }
    }
}

// ---------------- launch ----------------
extern "C" void kernel_launch(void* const* d_in, const int* in_sizes, int n_in,
                              void* d_out, int out_size) {
    const float* y  = (const float*)d_in[0];
    const float* ew = (const float*)d_in[1];
    const float* un = (const float*)d_in[2];
    float* out = (float*)d_out;

    init_kernel<<<1024, 256>>>(y, (const float2*)ew, (const float2*)un);
    persist_kernel<<<NBLOCKS, 256>>>(out);
}

// round 7
// speedup vs baseline: 1.0813x; 1.0813x over previous
#include <cuda_runtime.h>

// B=4, H=256, W=256 torus. mu-subsystem only. Persistent kernel, balanced:
// 128 blocks (1 per SM) x 512 threads; 16 warps x (9 rows x 32 cols) regs.
// Region 144x32, interior 128x16, T=8 per period, 13 periods (12x8 + 4).
#define BHW 262144
#define NBLOCKS 128

__device__ float  g_mu[2][BHW];   // mu ping-pong (per period)
__device__ float  g_v [2][BHW];   // momentum ping-pong
__device__ float4 g_c [BHW];      // 0.01*(ex, ey, eu0, el1)
__device__ float2 g_ac[BHW];      // 0.01*(2*uw1, uw2*y)
__device__ unsigned g_bar;        // global barrier counter

// ---------------- init: pack per-pixel constants (LR pre-folded) ----------
__global__ __launch_bounds__(256) void init_kernel(const float* __restrict__ y,
                                                   const float2* __restrict__ ew2,
                                                   const float2* __restrict__ un2) {
    const int p = blockIdx.x * 256 + threadIdx.x;
    const int base = p & ~65535;
    const int i    = p &  65535;
    const int row  = i & ~255;
    const int pu = base | ((i + 65280) & 65535);
    const int pl = base | row | ((i + 255) & 255);

    const float yv = y[p];
    const float2 e  = ew2[p];
    const float  eu = ew2[pu].x;
    const float  el = ew2[pl].y;
    const float2 u  = un2[p];

    g_mu[0][p] = yv;
    g_v [0][p] = 0.0f;
    g_c [p]    = make_float4(0.01f * e.x, 0.01f * e.y, 0.01f * eu, 0.01f * el);
    g_ac[p]    = make_float2(0.01f * 2.0f * u.x, 0.01f * u.y * yv);
    if (p == 0) g_bar = 0u;
}

// ---------------- persistent kernel ----------------
__global__ __launch_bounds__(512, 1) void persist_kernel(float* __restrict__ out) {
    __shared__ float s_top[2][16][32];   // each band's row-0 mu, double-buffered
    __shared__ float s_bot[2][16][32];   // each band's row-8 mu

    const int lane = threadIdx.x & 31;
    const int w    = threadIdx.x >> 5;           // band 0..15
    const int blk  = blockIdx.x;                 // 4 img x 2 vtile x 16 htile
    const int base = (blk >> 5) << 16;
    const int tv   = (blk >> 4) & 1;
    const int th   = blk & 15;
    const int gcol = (th * 16 - 8 + lane) & 255;     // region column (wrapped)
    const int r0   = tv * 128 - 8 + w * 9;           // band's first global row

    // cz[r] == cx[r-1]; only row 0 needs explicit cz0.
    float mu[9], v[9], cx[9], cy[9], cw[9], ax[9], ay[9], cz0;

    #pragma unroll
    for (int r = 0; r < 9; ++r) {
        const int p = base + (((r0 + r) & 255) << 8) + gcol;
        mu[r] = g_mu[0][p];
        v[r]  = g_v[0][p];
        const float4 c = g_c[p];
        cx[r] = c.x; cy[r] = c.y; cw[r] = c.w;
        if (r == 0) cz0 = c.z;
        const float2 a = g_ac[p];
        ax[r] = a.x; ay[r] = a.y;
    }

    unsigned target = 0;
    for (int per = 0; per < 13; ++per) {
        const int TT = (per < 12) ? 8 : 4;

        s_top[0][w][lane] = mu[0];
        s_bot[0][w][lane] = mu[8];
        __syncthreads();

        for (int it = 0; it < TT; ++it) {
            const int rb = it & 1;
            float old_above = (w > 0)  ? s_bot[rb][w - 1][lane] : mu[0];
            const float dn  = (w < 15) ? s_top[rb][w + 1][lane] : mu[8];

            #pragma unroll
            for (int r = 0; r < 9; ++r) {
                const float cur   = mu[r];
                const float below = (r < 8) ? mu[r + 1] : dn;
                const float left  = __shfl_up_sync(0xFFFFFFFFu, cur, 1);
                const float right = __shfl_down_sync(0xFFFFFFFFu, cur, 1);
                const float czr   = (r == 0) ? cz0 : cx[r - 1];

                float dmu = fmaf(ax[r], cur, ay[r]);   // already x0.01
                dmu = fmaf(cx[r], below, dmu);
                dmu = fmaf(cy[r], right, dmu);
                dmu = fmaf(czr,  old_above, dmu);
                dmu = fmaf(cw[r], left, dmu);

                v[r]  = fmaf(0.7f, v[r], dmu);
                mu[r] = fminf(fmaxf(cur + v[r], 0.0f), 63.0f);
                old_above = cur;
            }
            s_top[rb ^ 1][w][lane] = mu[0];
            s_bot[rb ^ 1][w][lane] = mu[8];
            __syncthreads();
        }

        const int d = (per + 1) & 1;

        // Write exact interior: region rows 8..135, cols 8..23.
        if (lane >= 8 && lane < 24) {
            #pragma unroll
            for (int r = 0; r < 9; ++r) {
                const int R = w * 9 + r;
                if (R >= 8 && R < 136) {
                    const int p = base + (((r0 + r) & 255) << 8) + gcol;
                    g_mu[d][p] = mu[r];
                    g_v [d][p] = v[r];
                    if (per == 12) out[p] = mu[r];
                }
            }
        }

        if (per == 12) break;

        // ---- global barrier ----
        __threadfence();
        __syncthreads();
        target += NBLOCKS;
        if (threadIdx.x == 0) {
            atomicAdd(&g_bar, 1u);
            while (*((volatile unsigned*)&g_bar) < target) { }
            __threadfence();
        }
        __syncthreads();

        // Reload halo cells' mu,v (interior stays in registers).
        #pragma unroll
        for (int r = 0; r < 9; ++r) {
            const int R = w * 9 + r;
            const bool interior = (R >= 8) && (R < 136) && (lane >= 8) && (lane < 24);
            if (!interior) {
                const int p = base + (((r0 + r) & 255) << 8) + gcol;
                mu[r] = g_mu[d][p];
                v[r]  = g_v[d][p];
            }
        }
    }
}

// ---------------- launch ----------------
extern "C" void kernel_launch(void* const* d_in, const int* in_sizes, int n_in,
                              void* d_out, int out_size) {
    const float* y  = (const float*)d_in[0];
    const float* ew = (const float*)d_in[1];
    const float* un = (const float*)d_in[2];
    float* out = (float*)d_out;

    init_kernel<<<1024, 256>>>(y, (const float2*)ew, (const float2*)un);
    persist_kernel<<<NBLOCKS, 512>>>(out);
}